// round 3
// baseline (speedup 1.0000x reference)
#include <cuda_runtime.h>
#include <cuda_bf16.h>
#include <cstdint>

#define N_NODES  100000
#define N_EDGES  1600000
#define N_GRAPHS 1000
#define D        128
#define NOUT     6
#define NB_SCAN  ((N_NODES + 1023) / 1024)   // 98

// ---------------- scratch (static device globals; no allocs allowed) ----------
__device__ __align__(16) float g_bufA[N_NODES * D];
__device__ __align__(16) float g_bufB[N_NODES * D];
__device__ int   g_rowptr[N_NODES + 1];
__device__ int   g_pos[N_NODES];          // doubles as histogram counts
__device__ int   g_col[N_EDGES];
__device__ int   g_bsum[NB_SCAN];
__device__ int   g_bscan[NB_SCAN];
__device__ __align__(16) float g_pooled[N_GRAPHS * D];
__device__ int   g_cnt[N_GRAPHS];
__device__ int   g_flag;                   // 1 = indices are int64, 0 = int32

// ---------------- helpers -----------------------------------------------------
__device__ __forceinline__ long long ld_idx(const void* p, long long i, int wide) {
    return wide ? ((const long long*)p)[i] : (long long)((const int*)p)[i];
}

__global__ void k_detect(const void* ei) {
    const int* p = (const int*)ei;
    int wide = 1;
    for (int i = 0; i < 64; i++) {
        if (p[2 * i + 1] != 0) { wide = 0; break; }
    }
    g_flag = wide;
}

__global__ void k_zero_scratch() {
    int i = blockIdx.x * blockDim.x + threadIdx.x;
    int total = N_NODES + N_GRAPHS * D + N_GRAPHS;
    for (; i < total; i += gridDim.x * blockDim.x) {
        if (i < N_NODES) g_pos[i] = 0;
        else if (i < N_NODES + N_GRAPHS * D) g_pooled[i - N_NODES] = 0.0f;
        else g_cnt[i - N_NODES - N_GRAPHS * D] = 0;
    }
}

__global__ void k_hist(const void* ei) {
    int wide = g_flag;
    int e = blockIdx.x * blockDim.x + threadIdx.x;
    for (; e < N_EDGES; e += gridDim.x * blockDim.x) {
        int dst = (int)ld_idx(ei, (long long)N_EDGES + e, wide);
        atomicAdd(&g_pos[dst], 1);
    }
}

__global__ void k_scan1() {
    __shared__ int s[1024];
    int t = threadIdx.x;
    int i = blockIdx.x * 1024 + t;
    int v = (i < N_NODES) ? g_pos[i] : 0;
    s[t] = v;
    __syncthreads();
    for (int off = 1; off < 1024; off <<= 1) {
        int x = (t >= off) ? s[t - off] : 0;
        __syncthreads();
        s[t] += x;
        __syncthreads();
    }
    if (i < N_NODES) g_rowptr[i + 1] = s[t];
    if (t == 1023) g_bsum[blockIdx.x] = s[1023];
}

__global__ void k_scan2() {
    int run = 0;
    for (int b = 0; b < NB_SCAN; b++) {
        int v = g_bsum[b];
        g_bscan[b] = run;
        run += v;
    }
}

__global__ void k_scan3() {
    int t = threadIdx.x;
    int i = blockIdx.x * 1024 + t;
    if (i < N_NODES) g_rowptr[i + 1] += g_bscan[blockIdx.x];
    if (i == 0) g_rowptr[0] = 0;
}

__global__ void k_fillpos() {
    int i = blockIdx.x * blockDim.x + threadIdx.x;
    for (; i < N_NODES; i += gridDim.x * blockDim.x) g_pos[i] = g_rowptr[i];
}

__global__ void k_fill(const void* ei) {
    int wide = g_flag;
    int e = blockIdx.x * blockDim.x + threadIdx.x;
    for (; e < N_EDGES; e += gridDim.x * blockDim.x) {
        int src = (int)ld_idx(ei, e, wide);
        int dst = (int)ld_idx(ei, (long long)N_EDGES + e, wide);
        int p = atomicAdd(&g_pos[dst], 1);
        g_col[p] = src;
    }
}

// agg[n] = x[n] + sum_{j in N(n)} x[j] ; warp per node, lane handles float4
__global__ void k_agg(const float* __restrict__ in, float* __restrict__ out) {
    int warp = (blockIdx.x * blockDim.x + threadIdx.x) >> 5;
    int lane = threadIdx.x & 31;
    if (warp >= N_NODES) return;
    const float4* in4 = (const float4*)in;
    float4* out4 = (float4*)out;
    float4 acc = in4[(long long)warp * 32 + lane];
    int beg = g_rowptr[warp], end = g_rowptr[warp + 1];
    for (int j = beg; j < end; j++) {
        int s = g_col[j];
        float4 v = in4[(long long)s * 32 + lane];
        acc.x += v.x; acc.y += v.y; acc.z += v.z; acc.w += v.w;
    }
    out4[(long long)warp * 32 + lane] = acc;
}

// ---------------- tensor-core GEMM (bf16 3-term split) ------------------------
// C[M x 128] = A[M x 128] @ W[128 x 128] + bias, optional relu
// A = Ahi + Alo (bf16 split), W = Whi + Wlo; C ~= Ahi@Whi + Ahi@Wlo + Alo@Whi
#define LDB 136                 // padded row length (bf16 elems); 272B stride
#define TILE_ELEMS (128 * LDB)  // 17408
#define SMEM_GEMM (4 * TILE_ELEMS * 2)  // 139264 bytes

__device__ __forceinline__ void ldsm4(uint32_t& r0, uint32_t& r1, uint32_t& r2, uint32_t& r3, uint32_t addr) {
    asm volatile("ldmatrix.sync.aligned.m8n8.x4.shared.b16 {%0,%1,%2,%3}, [%4];"
                 : "=r"(r0), "=r"(r1), "=r"(r2), "=r"(r3) : "r"(addr));
}
__device__ __forceinline__ void ldsm4t(uint32_t& r0, uint32_t& r1, uint32_t& r2, uint32_t& r3, uint32_t addr) {
    asm volatile("ldmatrix.sync.aligned.m8n8.x4.trans.shared.b16 {%0,%1,%2,%3}, [%4];"
                 : "=r"(r0), "=r"(r1), "=r"(r2), "=r"(r3) : "r"(addr));
}
__device__ __forceinline__ void mma_bf16(float* c, uint32_t a0, uint32_t a1, uint32_t a2, uint32_t a3,
                                         uint32_t b0, uint32_t b1) {
    asm volatile("mma.sync.aligned.m16n8k16.row.col.f32.bf16.bf16.f32 "
                 "{%0,%1,%2,%3}, {%4,%5,%6,%7}, {%8,%9}, {%0,%1,%2,%3};"
                 : "+f"(c[0]), "+f"(c[1]), "+f"(c[2]), "+f"(c[3])
                 : "r"(a0), "r"(a1), "r"(a2), "r"(a3), "r"(b0), "r"(b1));
}

__global__ __launch_bounds__(256, 1)
void k_gemm_t(const float* __restrict__ A, const float* __restrict__ W,
              const float* __restrict__ bias, float* __restrict__ C, int doRelu) {
    extern __shared__ __nv_bfloat16 sm[];
    __nv_bfloat16* sAhi = sm;
    __nv_bfloat16* sAlo = sm + TILE_ELEMS;
    __nv_bfloat16* sWhi = sm + 2 * TILE_ELEMS;
    __nv_bfloat16* sWlo = sm + 3 * TILE_ELEMS;
    const int t = threadIdx.x;
    const int blockRow = blockIdx.x * 128;

    // load + split A tile and full W into bf16 hi/lo smem
#pragma unroll
    for (int i = 0; i < 16; i++) {
        int lin = t + i * 256;              // 0..4095 float4s
        int row = lin >> 5;
        int col = (lin & 31) * 4;
        int o = row * LDB + col;
        // A
        float4 v = make_float4(0.f, 0.f, 0.f, 0.f);
        long long gr = blockRow + row;
        if (gr < N_NODES) v = *(const float4*)&A[gr * 128 + col];
        __nv_bfloat162 h01 = __floats2bfloat162_rn(v.x, v.y);
        __nv_bfloat162 h23 = __floats2bfloat162_rn(v.z, v.w);
        __nv_bfloat162 l01 = __floats2bfloat162_rn(v.x - __bfloat162float(h01.x),
                                                   v.y - __bfloat162float(h01.y));
        __nv_bfloat162 l23 = __floats2bfloat162_rn(v.z - __bfloat162float(h23.x),
                                                   v.w - __bfloat162float(h23.y));
        *(__nv_bfloat162*)&sAhi[o] = h01; *(__nv_bfloat162*)&sAhi[o + 2] = h23;
        *(__nv_bfloat162*)&sAlo[o] = l01; *(__nv_bfloat162*)&sAlo[o + 2] = l23;
        // W (contiguous 128x128)
        float4 wv = *(const float4*)&W[(long long)lin * 4];
        __nv_bfloat162 wh01 = __floats2bfloat162_rn(wv.x, wv.y);
        __nv_bfloat162 wh23 = __floats2bfloat162_rn(wv.z, wv.w);
        __nv_bfloat162 wl01 = __floats2bfloat162_rn(wv.x - __bfloat162float(wh01.x),
                                                    wv.y - __bfloat162float(wh01.y));
        __nv_bfloat162 wl23 = __floats2bfloat162_rn(wv.z - __bfloat162float(wh23.x),
                                                    wv.w - __bfloat162float(wh23.y));
        *(__nv_bfloat162*)&sWhi[o] = wh01; *(__nv_bfloat162*)&sWhi[o + 2] = wh23;
        *(__nv_bfloat162*)&sWlo[o] = wl01; *(__nv_bfloat162*)&sWlo[o + 2] = wl23;
    }
    __syncthreads();

    const int w = t >> 5, lane = t & 31;
    const int mbase = (w >> 1) * 32;        // 4 m-warps
    const int nbase = (w & 1) * 64;         // 2 n-warps
    const int lrow = lane & 15;
    const int lcol = (lane >> 4) * 8;

    float acc[2][8][4];
#pragma unroll
    for (int mi = 0; mi < 2; mi++)
#pragma unroll
        for (int nf = 0; nf < 8; nf++)
#pragma unroll
            for (int r = 0; r < 4; r++) acc[mi][nf][r] = 0.f;

    uint32_t sBase = (uint32_t)__cvta_generic_to_shared(sm);

#pragma unroll
    for (int pass = 0; pass < 3; pass++) {
        const int aOff = (pass == 2) ? TILE_ELEMS : 0;
        const int wOff = (pass == 1) ? 3 * TILE_ELEMS : 2 * TILE_ELEMS;
#pragma unroll
        for (int kk = 0; kk < 8; kk++) {
            const int k0 = kk * 16;
            uint32_t a[2][4];
            uint32_t addrA = sBase + 2u * (aOff + (mbase + lrow) * LDB + k0 + lcol);
            ldsm4(a[0][0], a[0][1], a[0][2], a[0][3], addrA);
            ldsm4(a[1][0], a[1][1], a[1][2], a[1][3], addrA + 2u * 16 * LDB);
            uint32_t b[4][4];
#pragma unroll
            for (int ni = 0; ni < 4; ni++) {
                uint32_t addrB = sBase + 2u * (wOff + (k0 + lrow) * LDB + nbase + ni * 16 + lcol);
                ldsm4t(b[ni][0], b[ni][1], b[ni][2], b[ni][3], addrB);
            }
#pragma unroll
            for (int mi = 0; mi < 2; mi++)
#pragma unroll
                for (int ni = 0; ni < 4; ni++) {
                    mma_bf16(acc[mi][2 * ni],     a[mi][0], a[mi][1], a[mi][2], a[mi][3], b[ni][0], b[ni][1]);
                    mma_bf16(acc[mi][2 * ni + 1], a[mi][0], a[mi][1], a[mi][2], a[mi][3], b[ni][2], b[ni][3]);
                }
        }
    }

    // epilogue: bias + optional relu, direct 8B stores
    const int cBase = nbase + 2 * (lane & 3);
    float2 bb[8];
#pragma unroll
    for (int nf = 0; nf < 8; nf++) bb[nf] = *(const float2*)&bias[cBase + nf * 8];

#pragma unroll
    for (int mi = 0; mi < 2; mi++) {
#pragma unroll
        for (int half = 0; half < 2; half++) {
            long long rr = blockRow + mbase + mi * 16 + (lane >> 2) + half * 8;
            if (rr >= N_NODES) continue;
#pragma unroll
            for (int nf = 0; nf < 8; nf++) {
                float2 o;
                o.x = acc[mi][nf][half * 2 + 0] + bb[nf].x;
                o.y = acc[mi][nf][half * 2 + 1] + bb[nf].y;
                if (doRelu) { o.x = fmaxf(o.x, 0.f); o.y = fmaxf(o.y, 0.f); }
                *(float2*)&C[rr * 128 + cBase + nf * 8] = o;
            }
        }
    }
}

// per-graph counts
__global__ void k_count(const void* batch) {
    int wide = g_flag;
    int n = blockIdx.x * blockDim.x + threadIdx.x;
    for (; n < N_NODES; n += gridDim.x * blockDim.x) {
        int g = (int)ld_idx(batch, n, wide);
        atomicAdd(&g_cnt[g], 1);
    }
}

#define NODES_PER_BLK 512
__global__ void k_pool(const float* __restrict__ h, const void* batch) {
    int wide = g_flag;
    int f = threadIdx.x;
    int base = blockIdx.x * NODES_PER_BLK;
    int end = base + NODES_PER_BLK;
    if (end > N_NODES) end = N_NODES;
    float run = 0.0f;
    int cur = -1;
    for (int n = base; n < end; n++) {
        int g = (int)ld_idx(batch, n, wide);
        if (g != cur) {
            if (cur >= 0) atomicAdd(&g_pooled[cur * D + f], run);
            cur = g;
            run = 0.0f;
        }
        run += h[(long long)n * D + f];
    }
    if (cur >= 0) atomicAdd(&g_pooled[cur * D + f], run);
}

__global__ void k_final(const float* __restrict__ Wlin, const float* __restrict__ blin,
                        float* __restrict__ out) {
    int g = blockIdx.x;
    int k = threadIdx.x; // 128
    float c = (float)g_cnt[g];
    if (c < 1.0f) c = 1.0f;
    float v = g_pooled[g * D + k] / c;
    __shared__ float red[128];
    for (int j = 0; j < NOUT; j++) {
        red[k] = v * Wlin[k * NOUT + j];
        __syncthreads();
        for (int s = 64; s > 0; s >>= 1) {
            if (k < s) red[k] += red[k + s];
            __syncthreads();
        }
        if (k == 0) out[g * NOUT + j] = red[0] + blin[j];
        __syncthreads();
    }
}

// ---------------- launch ------------------------------------------------------
extern "C" void kernel_launch(void* const* d_in, const int* in_sizes, int n_in,
                              void* d_out, int out_size) {
    const float* x    = (const float*)d_in[0];
    const void*  ei   = d_in[1];
    const void*  batch= d_in[2];
    const float* W1a  = (const float*)d_in[3];
    const float* b1a  = (const float*)d_in[4];
    const float* W1b  = (const float*)d_in[5];
    const float* b1b  = (const float*)d_in[6];
    const float* W2a  = (const float*)d_in[7];
    const float* b2a  = (const float*)d_in[8];
    const float* W2b  = (const float*)d_in[9];
    const float* b2b  = (const float*)d_in[10];
    const float* Wlin = (const float*)d_in[11];
    const float* blin = (const float*)d_in[12];
    float* out = (float*)d_out;

    float* bufA; cudaGetSymbolAddress((void**)&bufA, g_bufA);
    float* bufB; cudaGetSymbolAddress((void**)&bufB, g_bufB);

    static int smemSet = 0;
    if (!smemSet) {
        cudaFuncSetAttribute(k_gemm_t, cudaFuncAttributeMaxDynamicSharedMemorySize, SMEM_GEMM);
        smemSet = 1;
    }

    k_detect<<<1, 1>>>(ei);
    k_zero_scratch<<<448, 512>>>();
    k_hist<<<6250, 256>>>(ei);
    k_scan1<<<NB_SCAN, 1024>>>();
    k_scan2<<<1, 1>>>();
    k_scan3<<<NB_SCAN, 1024>>>();
    k_fillpos<<<392, 256>>>();
    k_fill<<<6250, 256>>>(ei);

    const int aggBlocks = (N_NODES * 32 + 255) / 256;
    const int gemmBlocks = (N_NODES + 127) / 128;   // 782

    // layer 1
    k_agg<<<aggBlocks, 256>>>(x, bufA);
    k_gemm_t<<<gemmBlocks, 256, SMEM_GEMM>>>(bufA, W1a, b1a, bufB, 1);
    k_gemm_t<<<gemmBlocks, 256, SMEM_GEMM>>>(bufB, W1b, b1b, bufA, 1);  // includes outer relu
    // layer 2
    k_agg<<<aggBlocks, 256>>>(bufA, bufB);
    k_gemm_t<<<gemmBlocks, 256, SMEM_GEMM>>>(bufB, W2a, b2a, bufA, 1);
    k_gemm_t<<<gemmBlocks, 256, SMEM_GEMM>>>(bufA, W2b, b2b, bufB, 0);
    // pool + classify
    k_count<<<392, 256>>>(batch);
    k_pool<<<(N_NODES + NODES_PER_BLK - 1) / NODES_PER_BLK, 128>>>(bufB, batch);
    k_final<<<N_GRAPHS, 128>>>(Wlin, blin, out);
}